// round 12
// baseline (speedup 1.0000x reference)
#include <cuda_runtime.h>

namespace {
constexpr int B=2, N=512, M=512, DQ=128, DK=128, DE=64, DKE=192, H=8, O=32, OUTD=128;
}

__device__ __align__(16) float g_qk  [(size_t)B*N*DKE*H];   // [b][n][i][h]
__device__ __align__(16) float g_keyT[(size_t)B*DK*M];      // [b][i][m]
__device__ __align__(16) float g_v   [(size_t)B*M*H*O];     // [b][m][h][o]
__device__ __align__(16) float g_attn[(size_t)B*H*N*M];
__device__ __align__(16) float g_mh  [(size_t)B*N*H*O];

typedef unsigned long long u64;
__device__ __forceinline__ u64 pack2(float lo, float hi) {
    u64 r; asm("mov.b64 %0, {%1,%2};" : "=l"(r) : "f"(lo), "f"(hi)); return r;
}
__device__ __forceinline__ void fma2(u64& d, u64 a, u64 b) {
    asm("fma.rn.f32x2 %0, %1, %2, %0;" : "+l"(d) : "l"(a), "l"(b));
}
__device__ __forceinline__ float2 unpack2(u64 v) {
    float2 r; asm("mov.b64 {%0,%1}, %2;" : "=f"(r.x), "=f"(r.y) : "l"(v)); return r;
}

// ---------------------------------------------------------------------------
// K_pre: fused keyT (blocks 0..127) | qk (128..255) | v (256..383)
// ---------------------------------------------------------------------------
__global__ __launch_bounds__(256) void k_pre(const float* __restrict__ key,
                                             const float* __restrict__ query,
                                             const float* __restrict__ Wq,
                                             const float* __restrict__ Wk,
                                             const float* __restrict__ value,
                                             const float* __restrict__ Wv) {
    __shared__ float sm[3072];
    const int t = threadIdx.x;

    if (blockIdx.x < 128) {            // ---- keyT ----
        float (*ts)[33] = (float(*)[33])sm;
        const int x=blockIdx.x, b=x>>6, mt=(x&63)>>2, it=x&3;
        const int m0=mt<<5, i0=it<<5;
        #pragma unroll
        for (int j=0;j<4;j++){int idx=t+256*j,r=idx>>5,c=idx&31;
            ts[r][c]=key[((size_t)b*M+m0+r)*DK+i0+c];}
        __syncthreads();
        #pragma unroll
        for (int j=0;j<4;j++){int idx=t+256*j,r=idx>>5,c=idx&31;
            g_keyT[((size_t)b*DK+i0+r)*M+m0+c]=ts[c][r];}
    } else if (blockIdx.x < 256) {     // ---- qk ----
        float (*xs)[DQ]  = (float(*)[DQ])sm;
        float (*qs)[H*O] = (float(*)[H*O])(sm + 8*DQ);
        const int xb=blockIdx.x-128, b=xb>>6, n0=(xb&63)<<3;
        #pragma unroll
        for (int j=0;j<4;j++){int idx=t+256*j,nl=idx>>7,d=idx&127;
            xs[nl][d]=query[((size_t)(b*N+n0+nl))*DQ+d];}
        __syncthreads();
        {
            const int h=t>>5,o=t&31;
            float acc[8];
            #pragma unroll
            for (int nl=0;nl<8;nl++) acc[nl]=0.f;
            const float* wq=Wq+((size_t)h*DQ)*O+o;
            for (int d=0;d<DQ;d++){float w=wq[(size_t)d*O];
                #pragma unroll
                for (int nl=0;nl<8;nl++) acc[nl]=fmaf(xs[nl][d],w,acc[nl]);}
            const float scale=0.17677669529663688f; // 1/sqrt(32)
            #pragma unroll
            for (int nl=0;nl<8;nl++) qs[nl][t]=acc[nl]*scale;
        }
        __syncthreads();
        #pragma unroll
        for (int j=0;j<6;j++){
            int p=t+256*j,h=p/DKE,i=p-h*DKE;
            const float* wk=Wk+((size_t)h*DKE+i)*O;
            float acc[8];
            #pragma unroll
            for (int nl=0;nl<8;nl++) acc[nl]=0.f;
            for (int o=0;o<O;o++){float w=wk[o];
                #pragma unroll
                for (int nl=0;nl<8;nl++) acc[nl]=fmaf(qs[nl][h*O+o],w,acc[nl]);}
            #pragma unroll
            for (int nl=0;nl<8;nl++)
                g_qk[((size_t)(b*N+n0+nl)*DKE+i)*H+h]=acc[nl];
        }
    } else {                           // ---- v ----
        float (*xs)[DK] = (float(*)[DK])sm;
        const int xb=blockIdx.x-256, b=xb>>6, m0=(xb&63)<<3;
        #pragma unroll
        for (int j=0;j<4;j++){int idx=t+256*j,ml=idx>>7,d=idx&127;
            xs[ml][d]=value[((size_t)(b*M+m0+ml))*DK+d];}
        __syncthreads();
        const int h=t>>5,o=t&31;
        float acc[8];
        #pragma unroll
        for (int ml=0;ml<8;ml++) acc[ml]=0.f;
        const float* wv=Wv+((size_t)h*DK)*O+o;
        for (int d=0;d<DK;d++){float w=wv[(size_t)d*O];
            #pragma unroll
            for (int ml=0;ml<8;ml++) acc[ml]=fmaf(xs[ml][d],w,acc[ml]);}
        #pragma unroll
        for (int ml=0;ml<8;ml++)
            g_v[(((size_t)(b*M+m0+ml))*H+h)*O+o]=acc[ml];
    }
}

// ---------------------------------------------------------------------------
// K2 v7: R9 v4 tile (2 n, 128 thr, m-quad) + block phase staggering.
// bid%3==1 blocks run edge phase first; 148%3=1 so co-resident blocks mix,
// letting key-phase compute cover edge-phase DRAM waits SM-wide.
// ---------------------------------------------------------------------------
__global__ __launch_bounds__(128,4) void k_attn(const float* __restrict__ edge) {
    __shared__ __align__(16) u64   qk2[2*DKE*H];   // 24.6 KB [n][i][h] pairs
    __shared__ __align__(16) float xs[8*516];      // 16.5 KB edge slice [i][m]
    __shared__ float redA[16*4], redB[16*4];

    const int x=blockIdx.x;            // B*N/2 = 512
    const int b=x>>8, n0=(x&255)<<1, t=threadIdx.x;
    const int w=t>>5, l=t&31;
    const int bN = b*N + n0;

    const float* gq=g_qk+(size_t)bN*(DKE*H);
    #pragma unroll
    for (int j=0;j<24;j++){float v=gq[t+128*j]; qk2[t+128*j]=pack2(v,v);}
    __syncthreads();

    u64 acc[2][8][2];
    #pragma unroll
    for (int n=0;n<2;n++)
        #pragma unroll
        for (int h=0;h<8;h++){acc[n][h][0]=0ull;acc[n][h][1]=0ull;}

    auto keyPhase=[&](){
        const ulonglong2* kT=(const ulonglong2*)(g_keyT+(size_t)b*DK*M);
        #pragma unroll 4
        for (int i=0;i<DK;i++){
            ulonglong2 X=kT[i*(M/4)+t];
            #pragma unroll
            for (int n=0;n<2;n++){
                const ulonglong2* A=(const ulonglong2*)(qk2+(n*DKE+i)*8);
                ulonglong2 a0=A[0],a1=A[1],a2=A[2],a3=A[3];
                fma2(acc[n][0][0],a0.x,X.x); fma2(acc[n][0][1],a0.x,X.y);
                fma2(acc[n][1][0],a0.y,X.x); fma2(acc[n][1][1],a0.y,X.y);
                fma2(acc[n][2][0],a1.x,X.x); fma2(acc[n][2][1],a1.x,X.y);
                fma2(acc[n][3][0],a1.y,X.x); fma2(acc[n][3][1],a1.y,X.y);
                fma2(acc[n][4][0],a2.x,X.x); fma2(acc[n][4][1],a2.x,X.y);
                fma2(acc[n][5][0],a2.y,X.x); fma2(acc[n][5][1],a2.y,X.y);
                fma2(acc[n][6][0],a3.x,X.x); fma2(acc[n][6][1],a3.x,X.y);
                fma2(acc[n][7][0],a3.y,X.x); fma2(acc[n][7][1],a3.y,X.y);
            }
        }
    };

    auto edgePhase=[&](){
        for (int n=0;n<2;n++){
            const float* eb=edge+((size_t)(bN+n)*M)*DE;
            for (int s=0;s<8;s++){
                __syncthreads();
                #pragma unroll
                for (int r=0;r<8;r++){
                    int id=r*128+t, m=id>>1, c=id&1;
                    float4 v=*(const float4*)(eb+(size_t)m*DE+s*8+4*c);
                    float* p=xs+(4*c)*516+m;
                    p[0]=v.x; p[516]=v.y; p[1032]=v.z; p[1548]=v.w;
                }
                __syncthreads();
                #pragma unroll
                for (int il=0;il<8;il++){
                    ulonglong2 X=*(const ulonglong2*)(xs+il*516+4*t);
                    const ulonglong2* A=(const ulonglong2*)(qk2+(n*DKE+DK+s*8+il)*8);
                    ulonglong2 a0=A[0],a1=A[1],a2=A[2],a3=A[3];
                    fma2(acc[n][0][0],a0.x,X.x); fma2(acc[n][0][1],a0.x,X.y);
                    fma2(acc[n][1][0],a0.y,X.x); fma2(acc[n][1][1],a0.y,X.y);
                    fma2(acc[n][2][0],a1.x,X.x); fma2(acc[n][2][1],a1.x,X.y);
                    fma2(acc[n][3][0],a1.y,X.x); fma2(acc[n][3][1],a1.y,X.y);
                    fma2(acc[n][4][0],a2.x,X.x); fma2(acc[n][4][1],a2.x,X.y);
                    fma2(acc[n][5][0],a2.y,X.x); fma2(acc[n][5][1],a2.y,X.y);
                    fma2(acc[n][6][0],a3.x,X.x); fma2(acc[n][6][1],a3.x,X.y);
                    fma2(acc[n][7][0],a3.y,X.x); fma2(acc[n][7][1],a3.y,X.y);
                }
            }
        }
    };

    if (blockIdx.x % 3 == 1){ edgePhase(); keyPhase(); }
    else                    { keyPhase(); edgePhase(); }
    __syncthreads();

    // ---- softmax over m (register logits, block reduce) ----
    #pragma unroll
    for (int n=0;n<2;n++)
        #pragma unroll
        for (int h=0;h<8;h++){
            float2 p0=unpack2(acc[n][h][0]), p1=unpack2(acc[n][h][1]);
            float mx=fmaxf(fmaxf(p0.x,p0.y),fmaxf(p1.x,p1.y));
            #pragma unroll
            for (int s=16;s>0;s>>=1) mx=fmaxf(mx,__shfl_xor_sync(0xffffffffu,mx,s));
            if (l==0) redA[(n*8+h)*4+w]=mx;
        }
    __syncthreads();
    #pragma unroll
    for (int n=0;n<2;n++)
        #pragma unroll
        for (int h=0;h<8;h++){
            const int c=n*8+h;
            float gm=fmaxf(fmaxf(redA[c*4+0],redA[c*4+1]),
                           fmaxf(redA[c*4+2],redA[c*4+3]));
            float2 p0=unpack2(acc[n][h][0]), p1=unpack2(acc[n][h][1]);
            p0.x=__expf(p0.x-gm); p0.y=__expf(p0.y-gm);
            p1.x=__expf(p1.x-gm); p1.y=__expf(p1.y-gm);
            acc[n][h][0]=pack2(p0.x,p0.y);
            acc[n][h][1]=pack2(p1.x,p1.y);
            float sum=(p0.x+p0.y)+(p1.x+p1.y);
            #pragma unroll
            for (int s=16;s>0;s>>=1) sum+=__shfl_xor_sync(0xffffffffu,sum,s);
            if (l==0) redB[c*4+w]=sum;
        }
    __syncthreads();
    #pragma unroll
    for (int n=0;n<2;n++)
        #pragma unroll
        for (int h=0;h<8;h++){
            const int c=n*8+h;
            float inv=1.f/(redB[c*4+0]+redB[c*4+1]+redB[c*4+2]+redB[c*4+3]);
            float2 p0=unpack2(acc[n][h][0]), p1=unpack2(acc[n][h][1]);
            float4 o=make_float4(p0.x*inv,p0.y*inv,p1.x*inv,p1.y*inv);
            *(float4*)(g_attn+(((size_t)b*H+h)*N+n0+n)*M+4*t)=o;
        }
}

// ---------------------------------------------------------------------------
// K3: mh = attn @ v. 512 blocks (b,h,16-n), 128 threads.
// ---------------------------------------------------------------------------
__global__ __launch_bounds__(128) void k_av() {
    const int x=blockIdx.x;              // 2*8*32 = 512
    const int b=x>>8, h=(x>>5)&7, n0=(x&31)<<4;
    const int t=threadIdx.x, nl=t>>3, og=t&7;
    __shared__ __align__(16) float at[16][132];
    __shared__ __align__(16) float vt[128][32];
    u64 a01=0ull, a23=0ull;
    for (int mt=0;mt<4;mt++){
        const int mb=mt<<7;
        #pragma unroll
        for (int j=0;j<4;j++){int idx=t+128*j,r=idx>>5,c=idx&31;
            *(float4*)&at[r][c*4]=
                *(const float4*)(g_attn+(((size_t)b*H+h)*N+n0+r)*M+mb+c*4);}
        #pragma unroll
        for (int j=0;j<8;j++){int idx=t+128*j,ml=idx>>3,c=idx&7;
            *(float4*)&vt[ml][c*4]=
                *(const float4*)(g_v+(((size_t)b*M+mb+ml)*H+h)*O+c*4);}
        __syncthreads();
        #pragma unroll 8
        for (int m=0;m<128;m++){
            float a=at[nl][m];
            u64 a2=pack2(a,a);
            ulonglong2 V=*(const ulonglong2*)&vt[m][og*4];
            fma2(a01,a2,V.x);
            fma2(a23,a2,V.y);
        }
        __syncthreads();
    }
    float2 x01=unpack2(a01), x23=unpack2(a23);
    float4 outv=make_float4(x01.x,x01.y,x23.x,x23.y);
    *(float4*)&g_mh[((size_t)(b*N+n0+nl)*H+h)*O+og*4]=outv;
}

// ---------------------------------------------------------------------------
// K4 v3: out = mh @ Wp + bias. 256 blocks (4 n), 512 thr = (jj, k-quarter).
// ---------------------------------------------------------------------------
__global__ __launch_bounds__(512) void k_proj(const float* __restrict__ Wp,
                                              const float* __restrict__ bias,
                                              float* __restrict__ out) {
    const int x=blockIdx.x;              // B*N/4 = 256
    const int b=x>>7, n0=(x&127)<<2, t=threadIdx.x;
    const int jj=t&127, kq=t>>7;
    __shared__ float mhs[4][H*O];
    __shared__ float red[3][4][128];

    #pragma unroll
    for (int j=0;j<2;j++){
        int idx=t+512*j, nl=idx>>8, c=idx&255;
        mhs[nl][c]=g_mh[(size_t)(b*N+n0+nl)*(H*O)+c];
    }
    __syncthreads();

    float acc[4]={0.f,0.f,0.f,0.f};
    const float* wp=Wp+(size_t)(kq*64)*OUTD+jj;
    const int kb=kq*64;
    #pragma unroll 8
    for (int k=0;k<64;k++){
        float wv=wp[(size_t)k*OUTD];
        #pragma unroll
        for (int n=0;n<4;n++) acc[n]=fmaf(mhs[n][kb+k],wv,acc[n]);
    }
    if (kq>0){
        #pragma unroll
        for (int n=0;n<4;n++) red[kq-1][n][jj]=acc[n];
    }
    __syncthreads();
    if (kq==0){
        float bv=bias[jj];
        #pragma unroll
        for (int n=0;n<4;n++){
            float r=acc[n]+red[0][n][jj]+red[1][n][jj]+red[2][n][jj]+bv;
            out[(size_t)(b*N+n0+n)*OUTD+jj]=r;
        }
    }
}

extern "C" void kernel_launch(void* const* d_in, const int* in_sizes, int n_in,
                              void* d_out, int out_size) {
    (void)in_sizes; (void)n_in; (void)out_size;
    const float* query=(const float*)d_in[0];
    const float* key  =(const float*)d_in[1];
    const float* value=(const float*)d_in[2];
    const float* edge =(const float*)d_in[3];
    const float* Wq   =(const float*)d_in[4];
    const float* Wk   =(const float*)d_in[5];
    const float* Wv   =(const float*)d_in[6];
    const float* Wp   =(const float*)d_in[7];
    const float* bias =(const float*)d_in[8];
    float* out=(float*)d_out;

    k_pre <<<384,        256>>>(key,query,Wq,Wk,value,Wv);
    k_attn<<<B*(N/2),    128>>>(edge);
    k_av  <<<B*H*(N/16), 128>>>();
    k_proj<<<B*(N/4),    512>>>(Wp,bias,out);
}

// round 13
// speedup vs baseline: 1.3615x; 1.3615x over previous
#include <cuda_runtime.h>

namespace {
constexpr int B=2, N=512, M=512, DQ=128, DK=128, DE=64, DKE=192, H=8, O=32, OUTD=128;
}

__device__ __align__(16) float g_qk  [(size_t)B*N*DKE*H];   // [b][n][i][h]
__device__ __align__(16) float g_keyT[(size_t)B*DK*M];      // [b][i][m]
__device__ __align__(16) float g_v   [(size_t)B*M*H*O];     // [b][m][h][o]
__device__ __align__(16) float g_attn[(size_t)B*H*N*M];
__device__ __align__(16) float g_mh  [(size_t)B*N*H*O];

typedef unsigned long long u64;
__device__ __forceinline__ u64 pack2(float lo, float hi) {
    u64 r; asm("mov.b64 %0, {%1,%2};" : "=l"(r) : "f"(lo), "f"(hi)); return r;
}
__device__ __forceinline__ void fma2(u64& d, u64 a, u64 b) {
    asm("fma.rn.f32x2 %0, %1, %2, %0;" : "+l"(d) : "l"(a), "l"(b));
}
__device__ __forceinline__ float2 unpack2(u64 v) {
    float2 r; asm("mov.b64 {%0,%1}, %2;" : "=f"(r.x), "=f"(r.y) : "l"(v)); return r;
}

// ---------------------------------------------------------------------------
// K0: key transpose -> g_keyT[b][i][m]
// ---------------------------------------------------------------------------
__global__ __launch_bounds__(256) void k_keyT(const float* __restrict__ key) {
    __shared__ float ts[32][33];
    const int x=blockIdx.x, b=x>>6, mt=(x&63)>>2, it=x&3;
    const int m0=mt<<5, i0=it<<5, t=threadIdx.x;
    #pragma unroll
    for (int j=0;j<4;j++){int idx=t+256*j,r=idx>>5,c=idx&31;
        ts[r][c]=key[((size_t)b*M+m0+r)*DK+i0+c];}
    __syncthreads();
    #pragma unroll
    for (int j=0;j<4;j++){int idx=t+256*j,r=idx>>5,c=idx&31;
        g_keyT[((size_t)b*DK+i0+r)*M+m0+c]=ts[c][r];}
}

// ---------------------------------------------------------------------------
// K1a: q = query@Wq/sqrt(32); qk = q@Wk^T -> g_qk [b][n][i][h]
// ---------------------------------------------------------------------------
__global__ __launch_bounds__(256) void k_qk(const float* __restrict__ query,
                                            const float* __restrict__ Wq,
                                            const float* __restrict__ Wk) {
    const int b=blockIdx.x>>6, n0=(blockIdx.x&63)<<3, t=threadIdx.x;
    __shared__ float xs[8][DQ];
    __shared__ float qs[8][H*O];
    #pragma unroll
    for (int j=0;j<4;j++){int idx=t+256*j,nl=idx>>7,d=idx&127;
        xs[nl][d]=query[((size_t)(b*N+n0+nl))*DQ+d];}
    __syncthreads();
    {
        const int h=t>>5,o=t&31;
        float acc[8];
        #pragma unroll
        for (int nl=0;nl<8;nl++) acc[nl]=0.f;
        const float* wq=Wq+((size_t)h*DQ)*O+o;
        for (int d=0;d<DQ;d++){float w=wq[(size_t)d*O];
            #pragma unroll
            for (int nl=0;nl<8;nl++) acc[nl]=fmaf(xs[nl][d],w,acc[nl]);}
        const float scale=0.17677669529663688f; // 1/sqrt(32)
        #pragma unroll
        for (int nl=0;nl<8;nl++) qs[nl][t]=acc[nl]*scale;
    }
    __syncthreads();
    #pragma unroll
    for (int j=0;j<6;j++){
        int p=t+256*j,h=p/DKE,i=p-h*DKE;
        const float* wk=Wk+((size_t)h*DKE+i)*O;
        float acc[8];
        #pragma unroll
        for (int nl=0;nl<8;nl++) acc[nl]=0.f;
        for (int o=0;o<O;o++){float w=wk[o];
            #pragma unroll
            for (int nl=0;nl<8;nl++) acc[nl]=fmaf(qs[nl][h*O+o],w,acc[nl]);}
        #pragma unroll
        for (int nl=0;nl<8;nl++)
            g_qk[((size_t)(b*N+n0+nl)*DKE+i)*H+h]=acc[nl];
    }
}

// ---------------------------------------------------------------------------
// K1b: v = value@Wv -> g_v [b][m][h][o]
// ---------------------------------------------------------------------------
__global__ __launch_bounds__(256) void k_v(const float* __restrict__ value,
                                           const float* __restrict__ Wv) {
    const int b=blockIdx.x>>6, m0=(blockIdx.x&63)<<3, t=threadIdx.x;
    __shared__ float xs[8][DK];
    #pragma unroll
    for (int j=0;j<4;j++){int idx=t+256*j,ml=idx>>7,d=idx&127;
        xs[ml][d]=value[((size_t)(b*M+m0+ml))*DK+d];}
    __syncthreads();
    const int h=t>>5,o=t&31;
    float acc[8];
    #pragma unroll
    for (int ml=0;ml<8;ml++) acc[ml]=0.f;
    const float* wv=Wv+((size_t)h*DK)*O+o;
    for (int d=0;d<DK;d++){float w=wv[(size_t)d*O];
        #pragma unroll
        for (int ml=0;ml<8;ml++) acc[ml]=fmaf(xs[ml][d],w,acc[ml]);}
    #pragma unroll
    for (int ml=0;ml<8;ml++)
        g_v[(((size_t)(b*M+m0+ml))*H+h)*O+o]=acc[ml];
}

// ---------------------------------------------------------------------------
// K2 v4 (exact R9 winner): block = 2 n, 128 threads, m-quad per thread.
// Launch index 3 so ncu profiles THIS kernel next round.
// ---------------------------------------------------------------------------
__global__ __launch_bounds__(128,4) void k_attn(const float* __restrict__ edge) {
    __shared__ __align__(16) u64   qk2[2*DKE*H];   // 24.6 KB [n][i][h] pairs
    __shared__ __align__(16) float xs[8*516];      // 16.5 KB edge slice [i][m]
    __shared__ float redA[16*4], redB[16*4];

    const int x=blockIdx.x;            // B*N/2 = 512
    const int b=x>>8, n0=(x&255)<<1, t=threadIdx.x;
    const int w=t>>5, l=t&31;

    const float* gq=g_qk+(size_t)(b*N+n0)*(DKE*H);
    #pragma unroll
    for (int j=0;j<24;j++){float v=gq[t+128*j]; qk2[t+128*j]=pack2(v,v);}
    __syncthreads();

    u64 acc[2][8][2];
    #pragma unroll
    for (int n=0;n<2;n++)
        #pragma unroll
        for (int h=0;h<8;h++){acc[n][h][0]=0ull;acc[n][h][1]=0ull;}

    // ---- key phase: X = keyT[b][i][4t..4t+3] ----
    {
        const ulonglong2* kT=(const ulonglong2*)(g_keyT+(size_t)b*DK*M);
        #pragma unroll 2
        for (int i=0;i<DK;i++){
            ulonglong2 X=kT[i*(M/4)+t];
            #pragma unroll
            for (int n=0;n<2;n++){
                const ulonglong2* A=(const ulonglong2*)(qk2+(n*DKE+i)*8);
                ulonglong2 a0=A[0],a1=A[1],a2=A[2],a3=A[3];
                fma2(acc[n][0][0],a0.x,X.x); fma2(acc[n][0][1],a0.x,X.y);
                fma2(acc[n][1][0],a0.y,X.x); fma2(acc[n][1][1],a0.y,X.y);
                fma2(acc[n][2][0],a1.x,X.x); fma2(acc[n][2][1],a1.x,X.y);
                fma2(acc[n][3][0],a1.y,X.x); fma2(acc[n][3][1],a1.y,X.y);
                fma2(acc[n][4][0],a2.x,X.x); fma2(acc[n][4][1],a2.x,X.y);
                fma2(acc[n][5][0],a2.y,X.x); fma2(acc[n][5][1],a2.y,X.y);
                fma2(acc[n][6][0],a3.x,X.x); fma2(acc[n][6][1],a3.x,X.y);
                fma2(acc[n][7][0],a3.y,X.x); fma2(acc[n][7][1],a3.y,X.y);
            }
        }
    }

    // ---- edge phase: per n, 8 slices of 8 i ----
    for (int n=0;n<2;n++){
        const float* eb=edge+((size_t)(b*N+n0+n)*M)*DE;
        for (int s=0;s<8;s++){
            __syncthreads();
            #pragma unroll
            for (int r=0;r<8;r++){
                int id=r*128+t, m=id>>1, c=id&1;
                float4 v=*(const float4*)(eb+(size_t)m*DE+s*8+4*c);
                float* p=xs+(4*c)*516+m;
                p[0]=v.x; p[516]=v.y; p[1032]=v.z; p[1548]=v.w;
            }
            __syncthreads();
            #pragma unroll
            for (int il=0;il<8;il++){
                ulonglong2 X=*(const ulonglong2*)(xs+il*516+4*t);
                const ulonglong2* A=(const ulonglong2*)(qk2+(n*DKE+DK+s*8+il)*8);
                ulonglong2 a0=A[0],a1=A[1],a2=A[2],a3=A[3];
                fma2(acc[n][0][0],a0.x,X.x); fma2(acc[n][0][1],a0.x,X.y);
                fma2(acc[n][1][0],a0.y,X.x); fma2(acc[n][1][1],a0.y,X.y);
                fma2(acc[n][2][0],a1.x,X.x); fma2(acc[n][2][1],a1.x,X.y);
                fma2(acc[n][3][0],a1.y,X.x); fma2(acc[n][3][1],a1.y,X.y);
                fma2(acc[n][4][0],a2.x,X.x); fma2(acc[n][4][1],a2.x,X.y);
                fma2(acc[n][5][0],a2.y,X.x); fma2(acc[n][5][1],a2.y,X.y);
                fma2(acc[n][6][0],a3.x,X.x); fma2(acc[n][6][1],a3.x,X.y);
                fma2(acc[n][7][0],a3.y,X.x); fma2(acc[n][7][1],a3.y,X.y);
            }
        }
    }
    __syncthreads();

    // ---- softmax over m (register logits, block reduce) ----
    #pragma unroll
    for (int n=0;n<2;n++)
        #pragma unroll
        for (int h=0;h<8;h++){
            float2 p0=unpack2(acc[n][h][0]), p1=unpack2(acc[n][h][1]);
            float mx=fmaxf(fmaxf(p0.x,p0.y),fmaxf(p1.x,p1.y));
            #pragma unroll
            for (int s=16;s>0;s>>=1) mx=fmaxf(mx,__shfl_xor_sync(0xffffffffu,mx,s));
            if (l==0) redA[(n*8+h)*4+w]=mx;
        }
    __syncthreads();
    #pragma unroll
    for (int n=0;n<2;n++)
        #pragma unroll
        for (int h=0;h<8;h++){
            const int c=n*8+h;
            float gm=fmaxf(fmaxf(redA[c*4+0],redA[c*4+1]),
                           fmaxf(redA[c*4+2],redA[c*4+3]));
            float2 p0=unpack2(acc[n][h][0]), p1=unpack2(acc[n][h][1]);
            p0.x=__expf(p0.x-gm); p0.y=__expf(p0.y-gm);
            p1.x=__expf(p1.x-gm); p1.y=__expf(p1.y-gm);
            acc[n][h][0]=pack2(p0.x,p0.y);
            acc[n][h][1]=pack2(p1.x,p1.y);
            float sum=(p0.x+p0.y)+(p1.x+p1.y);
            #pragma unroll
            for (int s=16;s>0;s>>=1) sum+=__shfl_xor_sync(0xffffffffu,sum,s);
            if (l==0) redB[c*4+w]=sum;
        }
    __syncthreads();
    #pragma unroll
    for (int n=0;n<2;n++)
        #pragma unroll
        for (int h=0;h<8;h++){
            const int c=n*8+h;
            float inv=1.f/(redB[c*4+0]+redB[c*4+1]+redB[c*4+2]+redB[c*4+3]);
            float2 p0=unpack2(acc[n][h][0]), p1=unpack2(acc[n][h][1]);
            float4 o=make_float4(p0.x*inv,p0.y*inv,p1.x*inv,p1.y*inv);
            *(float4*)(g_attn+(((size_t)b*H+h)*N+n0+n)*M+4*t)=o;
        }
}

// ---------------------------------------------------------------------------
// K3: mh = attn @ v. 512 blocks (b,h,16-n), 128 threads.
// ---------------------------------------------------------------------------
__global__ __launch_bounds__(128) void k_av() {
    const int x=blockIdx.x;              // 2*8*32 = 512
    const int b=x>>8, h=(x>>5)&7, n0=(x&31)<<4;
    const int t=threadIdx.x, nl=t>>3, og=t&7;
    __shared__ __align__(16) float at[16][132];
    __shared__ __align__(16) float vt[128][32];
    u64 a01=0ull, a23=0ull;
    for (int mt=0;mt<4;mt++){
        const int mb=mt<<7;
        #pragma unroll
        for (int j=0;j<4;j++){int idx=t+128*j,r=idx>>5,c=idx&31;
            *(float4*)&at[r][c*4]=
                *(const float4*)(g_attn+(((size_t)b*H+h)*N+n0+r)*M+mb+c*4);}
        #pragma unroll
        for (int j=0;j<8;j++){int idx=t+128*j,ml=idx>>3,c=idx&7;
            *(float4*)&vt[ml][c*4]=
                *(const float4*)(g_v+(((size_t)b*M+mb+ml)*H+h)*O+c*4);}
        __syncthreads();
        #pragma unroll 8
        for (int m=0;m<128;m++){
            float a=at[nl][m];
            u64 a2=pack2(a,a);
            ulonglong2 V=*(const ulonglong2*)&vt[m][og*4];
            fma2(a01,a2,V.x);
            fma2(a23,a2,V.y);
        }
        __syncthreads();
    }
    float2 x01=unpack2(a01), x23=unpack2(a23);
    float4 outv=make_float4(x01.x,x01.y,x23.x,x23.y);
    *(float4*)&g_mh[((size_t)(b*N+n0+nl)*H+h)*O+og*4]=outv;
}

// ---------------------------------------------------------------------------
// K4 v3: out = mh @ Wp + bias. 256 blocks (4 n), 512 thr = (jj, k-quarter).
// ---------------------------------------------------------------------------
__global__ __launch_bounds__(512) void k_proj(const float* __restrict__ Wp,
                                              const float* __restrict__ bias,
                                              float* __restrict__ out) {
    const int x=blockIdx.x;              // B*N/4 = 256
    const int b=x>>7, n0=(x&127)<<2, t=threadIdx.x;
    const int jj=t&127, kq=t>>7;
    __shared__ float mhs[4][H*O];
    __shared__ float red[3][4][128];

    #pragma unroll
    for (int j=0;j<2;j++){
        int idx=t+512*j, nl=idx>>8, c=idx&255;
        mhs[nl][c]=g_mh[(size_t)(b*N+n0+nl)*(H*O)+c];
    }
    __syncthreads();

    float acc[4]={0.f,0.f,0.f,0.f};
    const float* wp=Wp+(size_t)(kq*64)*OUTD+jj;
    const int kb=kq*64;
    #pragma unroll 8
    for (int k=0;k<64;k++){
        float wv=wp[(size_t)k*OUTD];
        #pragma unroll
        for (int n=0;n<4;n++) acc[n]=fmaf(mhs[n][kb+k],wv,acc[n]);
    }
    if (kq>0){
        #pragma unroll
        for (int n=0;n<4;n++) red[kq-1][n][jj]=acc[n];
    }
    __syncthreads();
    if (kq==0){
        float bv=bias[jj];
        #pragma unroll
        for (int n=0;n<4;n++){
            float r=acc[n]+red[0][n][jj]+red[1][n][jj]+red[2][n][jj]+bv;
            out[(size_t)(b*N+n0+n)*OUTD+jj]=r;
        }
    }
}

extern "C" void kernel_launch(void* const* d_in, const int* in_sizes, int n_in,
                              void* d_out, int out_size) {
    (void)in_sizes; (void)n_in; (void)out_size;
    const float* query=(const float*)d_in[0];
    const float* key  =(const float*)d_in[1];
    const float* value=(const float*)d_in[2];
    const float* edge =(const float*)d_in[3];
    const float* Wq   =(const float*)d_in[4];
    const float* Wk   =(const float*)d_in[5];
    const float* Wv   =(const float*)d_in[6];
    const float* Wp   =(const float*)d_in[7];
    const float* bias =(const float*)d_in[8];
    float* out=(float*)d_out;

    k_keyT<<<B*16*4,     256>>>(key);            // launch 0
    k_qk  <<<B*(N/8),    256>>>(query,Wq,Wk);    // launch 1
    k_v   <<<B*(M/8),    256>>>(value,Wv);       // launch 2
    k_attn<<<B*(N/2),    128>>>(edge);           // launch 3  <- profiled slot
    k_av  <<<B*H*(N/16), 128>>>();               // launch 4
    k_proj<<<B*(N/4),    512>>>(Wp,bias,out);    // launch 5
}

// round 15
// speedup vs baseline: 1.3804x; 1.0139x over previous
#include <cuda_runtime.h>

namespace {
constexpr int B=2, N=512, M=512, DQ=128, DK=128, DE=64, DKE=192, H=8, O=32, OUTD=128;
}

typedef unsigned long long u64;

__device__ __align__(16) float g_qk  [(size_t)B*N*DKE*H];   // [b][n][i][h]
__device__ __align__(16) u64   g_qkp [(size_t)B*H*DK*N];    // [b][h][i][n] {q,q} pairs
__device__ __align__(16) float g_keyT[(size_t)B*DK*M];      // [b][i][m]
__device__ __align__(16) float g_v   [(size_t)B*M*H*O];     // [b][m][h][o]
__device__ __align__(16) float g_attn[(size_t)B*H*N*M];     // key logits, then attn
__device__ __align__(16) float g_mh  [(size_t)B*N*H*O];

__device__ __forceinline__ u64 pack2(float lo, float hi) {
    u64 r; asm("mov.b64 %0, {%1,%2};" : "=l"(r) : "f"(lo), "f"(hi)); return r;
}
__device__ __forceinline__ void fma2(u64& d, u64 a, u64 b) {
    asm("fma.rn.f32x2 %0, %1, %2, %0;" : "+l"(d) : "l"(a), "l"(b));
}
__device__ __forceinline__ float2 unpack2(u64 v) {
    float2 r; asm("mov.b64 {%0,%1}, %2;" : "=f"(r.x), "=f"(r.y) : "l"(v)); return r;
}

// ---------------------------------------------------------------------------
// K_pre: fused keyT (blocks 0..127) | qk (+qkp pairs) (128..255) | v (256..383)
// ---------------------------------------------------------------------------
__global__ __launch_bounds__(256) void k_pre(const float* __restrict__ key,
                                             const float* __restrict__ query,
                                             const float* __restrict__ Wq,
                                             const float* __restrict__ Wk,
                                             const float* __restrict__ value,
                                             const float* __restrict__ Wv) {
    __shared__ float sm[3072];
    const int t = threadIdx.x;

    if (blockIdx.x < 128) {            // ---- keyT ----
        float (*ts)[33] = (float(*)[33])sm;
        const int x=blockIdx.x, b=x>>6, mt=(x&63)>>2, it=x&3;
        const int m0=mt<<5, i0=it<<5;
        #pragma unroll
        for (int j=0;j<4;j++){int idx=t+256*j,r=idx>>5,c=idx&31;
            ts[r][c]=key[((size_t)b*M+m0+r)*DK+i0+c];}
        __syncthreads();
        #pragma unroll
        for (int j=0;j<4;j++){int idx=t+256*j,r=idx>>5,c=idx&31;
            g_keyT[((size_t)b*DK+i0+r)*M+m0+c]=ts[c][r];}
    } else if (blockIdx.x < 256) {     // ---- qk ----
        float (*xs)[DQ]  = (float(*)[DQ])sm;
        float (*qs)[H*O] = (float(*)[H*O])(sm + 8*DQ);
        const int xb=blockIdx.x-128, b=xb>>6, n0=(xb&63)<<3;
        #pragma unroll
        for (int j=0;j<4;j++){int idx=t+256*j,nl=idx>>7,d=idx&127;
            xs[nl][d]=query[((size_t)(b*N+n0+nl))*DQ+d];}
        __syncthreads();
        {
            const int h=t>>5,o=t&31;
            float acc[8];
            #pragma unroll
            for (int nl=0;nl<8;nl++) acc[nl]=0.f;
            const float* wq=Wq+((size_t)h*DQ)*O+o;
            for (int d=0;d<DQ;d++){float w=wq[(size_t)d*O];
                #pragma unroll
                for (int nl=0;nl<8;nl++) acc[nl]=fmaf(xs[nl][d],w,acc[nl]);}
            const float scale=0.17677669529663688f; // 1/sqrt(32)
            #pragma unroll
            for (int nl=0;nl<8;nl++) qs[nl][t]=acc[nl]*scale;
        }
        __syncthreads();
        #pragma unroll
        for (int j=0;j<6;j++){
            int p=t+256*j,h=p/DKE,i=p-h*DKE;
            const float* wk=Wk+((size_t)h*DKE+i)*O;
            float acc[8];
            #pragma unroll
            for (int nl=0;nl<8;nl++) acc[nl]=0.f;
            for (int o=0;o<O;o++){float w=wk[o];
                #pragma unroll
                for (int nl=0;nl<8;nl++) acc[nl]=fmaf(qs[nl][h*O+o],w,acc[nl]);}
            #pragma unroll
            for (int nl=0;nl<8;nl++)
                g_qk[((size_t)(b*N+n0+nl)*DKE+i)*H+h]=acc[nl];
            if (i < DK){
                #pragma unroll
                for (int nl=0;nl<8;nl++)
                    g_qkp[((size_t)(b*H+h)*DK+i)*N + n0+nl]=pack2(acc[nl],acc[nl]);
            }
        }
    } else {                           // ---- v ----
        float (*xs)[DK] = (float(*)[DK])sm;
        const int xb=blockIdx.x-256, b=xb>>6, m0=(xb&63)<<3;
        #pragma unroll
        for (int j=0;j<4;j++){int idx=t+256*j,ml=idx>>7,d=idx&127;
            xs[ml][d]=value[((size_t)(b*M+m0+ml))*DK+d];}
        __syncthreads();
        const int h=t>>5,o=t&31;
        float acc[8];
        #pragma unroll
        for (int ml=0;ml<8;ml++) acc[ml]=0.f;
        const float* wv=Wv+((size_t)h*DK)*O+o;
        for (int d=0;d<DK;d++){float w=wv[(size_t)d*O];
            #pragma unroll
            for (int ml=0;ml<8;ml++) acc[ml]=fmaf(xs[ml][d],w,acc[ml]);}
        #pragma unroll
        for (int ml=0;ml<8;ml++)
            g_v[(((size_t)(b*M+m0+ml))*H+h)*O+o]=acc[ml];
    }
}

// ---------------------------------------------------------------------------
// K_key: key logits GEMM. Block = (b,h,64n,64m), 256 thr, 4n x 4m / thread.
// FIX vs R13: A-tile load now covers all 64 i rows (j<8, 2048 ulonglong2).
// ---------------------------------------------------------------------------
__global__ __launch_bounds__(256) void k_key() {
    __shared__ __align__(16) u64   As[64*64];   // 32 KB [i][n] pairs
    __shared__ __align__(16) float Bs[64*64];   // 16 KB [i][m]
    const int x=blockIdx.x;                     // 1024
    const int mt=x&7, nt=(x>>3)&7, h=(x>>6)&7, b=x>>9;
    const int t=threadIdx.x, tm=t&15, tn=t>>4;

    u64 acc[4][2];
    #pragma unroll
    for (int k=0;k<4;k++){acc[k][0]=0ull;acc[k][1]=0ull;}

    const u64*   Ab = g_qkp + ((size_t)(b*H+h)*DK)*N + nt*64;
    const float* Bb = g_keyT + ((size_t)b*DK)*M + mt*64;

    for (int kt=0;kt<2;kt++){
        #pragma unroll
        for (int j=0;j<8;j++){                 // 2048 ulonglong2 = full 64x64
            int idx=t+256*j, r=idx>>5, c=idx&31;
            ((ulonglong2*)As)[idx] =
                *(const ulonglong2*)(Ab + (size_t)(kt*64+r)*N + c*2);
        }
        #pragma unroll
        for (int j=0;j<4;j++){
            int idx=t+256*j, r=idx>>4, c=idx&15;
            ((float4*)Bs)[idx] =
                *(const float4*)(Bb + (size_t)(kt*64+r)*M + c*4);
        }
        __syncthreads();
        #pragma unroll 4
        for (int i=0;i<64;i++){
            ulonglong2 a01=*(const ulonglong2*)(As+i*64+tn*4);
            ulonglong2 a23=*(const ulonglong2*)(As+i*64+tn*4+2);
            ulonglong2 Bv =*(const ulonglong2*)(Bs+i*64+tm*4);
            fma2(acc[0][0],a01.x,Bv.x); fma2(acc[0][1],a01.x,Bv.y);
            fma2(acc[1][0],a01.y,Bv.x); fma2(acc[1][1],a01.y,Bv.y);
            fma2(acc[2][0],a23.x,Bv.x); fma2(acc[2][1],a23.x,Bv.y);
            fma2(acc[3][0],a23.y,Bv.x); fma2(acc[3][1],a23.y,Bv.y);
        }
        __syncthreads();
    }
    #pragma unroll
    for (int k=0;k<4;k++){
        float2 p0=unpack2(acc[k][0]), p1=unpack2(acc[k][1]);
        float4 o=make_float4(p0.x,p0.y,p1.x,p1.y);
        int n=nt*64+tn*4+k, m=mt*64+tm*4;
        *(float4*)(g_attn+(((size_t)b*H+h)*N+n)*M+m)=o;
    }
}

// ---------------------------------------------------------------------------
// K_attn v8: edge logits + merge key logits + softmax. 1 n, 128 thr, m-quad.
// ---------------------------------------------------------------------------
__global__ __launch_bounds__(128,5) void k_attn(const float* __restrict__ edge) {
    __shared__ __align__(16) u64   qk2[DE*H];    // 4 KB edge pairs [i][h]
    __shared__ __align__(16) float xs[2][8*516]; // 33 KB double-buffered slice
    __shared__ float redA[8*4], redB[8*4];

    const int x=blockIdx.x;            // B*N = 1024
    const int b=x>>9, n=x&511, t=threadIdx.x;
    const int w=t>>5, l=t&31;

    const float* gq=g_qk+(size_t)x*(DKE*H)+DK*H;
    #pragma unroll
    for (int j=0;j<4;j++){float v=gq[t+128*j]; qk2[t+128*j]=pack2(v,v);}
    __syncthreads();

    u64 acc[8][2];
    #pragma unroll
    for (int h=0;h<8;h++){acc[h][0]=0ull;acc[h][1]=0ull;}

    const float* eb=edge+(size_t)x*M*DE;
    float4 pf[8];
    #pragma unroll
    for (int r=0;r<8;r++){int id=r*128+t,m=id>>1,c=id&1;
        pf[r]=*(const float4*)(eb+(size_t)m*DE+4*c);}

    for (int s=0;s<8;s++){
        float* xb=xs[s&1];
        #pragma unroll
        for (int r=0;r<8;r++){int id=r*128+t,m=id>>1,c=id&1;
            float* p=xb+(4*c)*516+m;
            p[0]=pf[r].x; p[516]=pf[r].y; p[1032]=pf[r].z; p[1548]=pf[r].w;}
        __syncthreads();
        if (s<7){
            #pragma unroll
            for (int r=0;r<8;r++){int id=r*128+t,m=id>>1,c=id&1;
                pf[r]=*(const float4*)(eb+(size_t)m*DE+(s+1)*8+4*c);}
        }
        #pragma unroll
        for (int il=0;il<8;il++){
            ulonglong2 X=*(const ulonglong2*)(xb+il*516+4*t);
            const ulonglong2* A=(const ulonglong2*)(qk2+(s*8+il)*8);
            ulonglong2 a0=A[0],a1=A[1],a2=A[2],a3=A[3];
            fma2(acc[0][0],a0.x,X.x); fma2(acc[0][1],a0.x,X.y);
            fma2(acc[1][0],a0.y,X.x); fma2(acc[1][1],a0.y,X.y);
            fma2(acc[2][0],a1.x,X.x); fma2(acc[2][1],a1.x,X.y);
            fma2(acc[3][0],a1.y,X.x); fma2(acc[3][1],a1.y,X.y);
            fma2(acc[4][0],a2.x,X.x); fma2(acc[4][1],a2.x,X.y);
            fma2(acc[5][0],a2.y,X.x); fma2(acc[5][1],a2.y,X.y);
            fma2(acc[6][0],a3.x,X.x); fma2(acc[6][1],a3.x,X.y);
            fma2(acc[7][0],a3.y,X.x); fma2(acc[7][1],a3.y,X.y);
        }
    }

    // merge key logits from g_attn
    #pragma unroll
    for (int h=0;h<8;h++){
        float4 kv=*(const float4*)(g_attn+(((size_t)b*H+h)*N+n)*M+4*t);
        float2 p0=unpack2(acc[h][0]), p1=unpack2(acc[h][1]);
        acc[h][0]=pack2(p0.x+kv.x, p0.y+kv.y);
        acc[h][1]=pack2(p1.x+kv.z, p1.y+kv.w);
    }

    // softmax over m
    #pragma unroll
    for (int h=0;h<8;h++){
        float2 p0=unpack2(acc[h][0]), p1=unpack2(acc[h][1]);
        float mx=fmaxf(fmaxf(p0.x,p0.y),fmaxf(p1.x,p1.y));
        #pragma unroll
        for (int s=16;s>0;s>>=1) mx=fmaxf(mx,__shfl_xor_sync(0xffffffffu,mx,s));
        if (l==0) redA[h*4+w]=mx;
    }
    __syncthreads();
    #pragma unroll
    for (int h=0;h<8;h++){
        float gm=fmaxf(fmaxf(redA[h*4+0],redA[h*4+1]),
                       fmaxf(redA[h*4+2],redA[h*4+3]));
        float2 p0=unpack2(acc[h][0]), p1=unpack2(acc[h][1]);
        p0.x=__expf(p0.x-gm); p0.y=__expf(p0.y-gm);
        p1.x=__expf(p1.x-gm); p1.y=__expf(p1.y-gm);
        acc[h][0]=pack2(p0.x,p0.y);
        acc[h][1]=pack2(p1.x,p1.y);
        float sum=(p0.x+p0.y)+(p1.x+p1.y);
        #pragma unroll
        for (int s=16;s>0;s>>=1) sum+=__shfl_xor_sync(0xffffffffu,sum,s);
        if (l==0) redB[h*4+w]=sum;
    }
    __syncthreads();
    #pragma unroll
    for (int h=0;h<8;h++){
        float inv=1.f/(redB[h*4+0]+redB[h*4+1]+redB[h*4+2]+redB[h*4+3]);
        float2 p0=unpack2(acc[h][0]), p1=unpack2(acc[h][1]);
        float4 o=make_float4(p0.x*inv,p0.y*inv,p1.x*inv,p1.y*inv);
        *(float4*)(g_attn+(((size_t)b*H+h)*N+n)*M+4*t)=o;
    }
}

// ---------------------------------------------------------------------------
// K3: mh = attn @ v. 512 blocks (b,h,16-n), 128 threads.
// ---------------------------------------------------------------------------
__global__ __launch_bounds__(128) void k_av() {
    const int x=blockIdx.x;
    const int b=x>>8, h=(x>>5)&7, n0=(x&31)<<4;
    const int t=threadIdx.x, nl=t>>3, og=t&7;
    __shared__ __align__(16) float at[16][132];
    __shared__ __align__(16) float vt[128][32];
    u64 a01=0ull, a23=0ull;
    for (int mt=0;mt<4;mt++){
        const int mb=mt<<7;
        #pragma unroll
        for (int j=0;j<4;j++){int idx=t+128*j,r=idx>>5,c=idx&31;
            *(float4*)&at[r][c*4]=
                *(const float4*)(g_attn+(((size_t)b*H+h)*N+n0+r)*M+mb+c*4);}
        #pragma unroll
        for (int j=0;j<8;j++){int idx=t+128*j,ml=idx>>3,c=idx&7;
            *(float4*)&vt[ml][c*4]=
                *(const float4*)(g_v+(((size_t)b*M+mb+ml)*H+h)*O+c*4);}
        __syncthreads();
        #pragma unroll 8
        for (int m=0;m<128;m++){
            float a=at[nl][m];
            u64 a2=pack2(a,a);
            ulonglong2 V=*(const ulonglong2*)&vt[m][og*4];
            fma2(a01,a2,V.x);
            fma2(a23,a2,V.y);
        }
        __syncthreads();
    }
    float2 x01=unpack2(a01), x23=unpack2(a23);
    float4 outv=make_float4(x01.x,x01.y,x23.x,x23.y);
    *(float4*)&g_mh[((size_t)(b*N+n0+nl)*H+h)*O+og*4]=outv;
}

// ---------------------------------------------------------------------------
// K4 v3: out = mh @ Wp + bias. 256 blocks (4 n), 512 thr = (jj, k-quarter).
// ---------------------------------------------------------------------------
__global__ __launch_bounds__(512) void k_proj(const float* __restrict__ Wp,
                                              const float* __restrict__ bias,
                                              float* __restrict__ out) {
    const int x=blockIdx.x;
    const int b=x>>7, n0=(x&127)<<2, t=threadIdx.x;
    const int jj=t&127, kq=t>>7;
    __shared__ float mhs[4][H*O];
    __shared__ float red[3][4][128];

    #pragma unroll
    for (int j=0;j<2;j++){
        int idx=t+512*j, nl=idx>>8, c=idx&255;
        mhs[nl][c]=g_mh[(size_t)(b*N+n0+nl)*(H*O)+c];
    }
    __syncthreads();

    float acc[4]={0.f,0.f,0.f,0.f};
    const float* wp=Wp+(size_t)(kq*64)*OUTD+jj;
    const int kb=kq*64;
    #pragma unroll 8
    for (int k=0;k<64;k++){
        float wv=wp[(size_t)k*OUTD];
        #pragma unroll
        for (int n=0;n<4;n++) acc[n]=fmaf(mhs[n][kb+k],wv,acc[n]);
    }
    if (kq>0){
        #pragma unroll
        for (int n=0;n<4;n++) red[kq-1][n][jj]=acc[n];
    }
    __syncthreads();
    if (kq==0){
        float bv=bias[jj];
        #pragma unroll
        for (int n=0;n<4;n++){
            float r=acc[n]+red[0][n][jj]+red[1][n][jj]+red[2][n][jj]+bv;
            out[(size_t)(b*N+n0+n)*OUTD+jj]=r;
        }
    }
}

extern "C" void kernel_launch(void* const* d_in, const int* in_sizes, int n_in,
                              void* d_out, int out_size) {
    (void)in_sizes; (void)n_in; (void)out_size;
    const float* query=(const float*)d_in[0];
    const float* key  =(const float*)d_in[1];
    const float* value=(const float*)d_in[2];
    const float* edge =(const float*)d_in[3];
    const float* Wq   =(const float*)d_in[4];
    const float* Wk   =(const float*)d_in[5];
    const float* Wv   =(const float*)d_in[6];
    const float* Wp   =(const float*)d_in[7];
    const float* bias =(const float*)d_in[8];
    float* out=(float*)d_out;

    k_pre <<<384,        256>>>(key,query,Wq,Wk,value,Wv);
    k_key <<<1024,       256>>>();
    k_attn<<<B*N,        128>>>(edge);
    k_av  <<<B*H*(N/16), 128>>>();
    k_proj<<<B*(N/4),    512>>>(Wp,bias,out);
}